// round 12
// baseline (speedup 1.0000x reference)
#include <cuda_runtime.h>
#include <cuda_bf16.h>

// Problem constants: B=512, S=32768, alpha=0.1, beta=0.9
#define B_CONST 512
#define S_CONST 32768

// log(0.1), log(0.9). Note log(1-alpha)=log(beta), log(1-beta)=log(alpha).
#define LOG_A   (-2.3025850929940457f)   // log(0.1)
#define LOG_1A  (-0.10536051565782628f)  // log(0.9)
#define LOG_B   (-0.10536051565782628f)  // log(0.9)
#define LOG_1B  (-2.3025850929940457f)   // log(0.1)

constexpr int THREADS = 256;              // 8 warps
constexpr int ITERS   = 8;                // float4-iterations per warp
constexpr int WSEG    = ITERS * 64;       // 512 s-values per warp
constexpr int CHUNK   = (THREADS / 32) * WSEG;   // 4096 s per block
constexpr int BPR     = S_CONST / CHUNK;  // 8 blocks per row
constexpr int GRID    = B_CONST * BPR;    // 4096 blocks
constexpr unsigned FULL = 0xffffffffu;

__device__ float        g_partials[GRID];
__device__ unsigned int g_count;          // zero-init; spinner resets

// KL transition term: prev=(pp0,pp1), curr=(q0,q1); logs precomputed.
__device__ __forceinline__ float div_term_l(float pp0, float pp1,
                                            float q0, float q1,
                                            float l0, float l1)
{
    float t1 = q1 * (l1 - LOG_B)  + q0 * (l0 - LOG_1B);
    float t2 = q1 * (l1 - LOG_1B) + q0 * (l0 - LOG_B);
    return pp1 * t1 + pp0 * t2;
}

__global__ __launch_bounds__(THREADS)
void ekl_kernel(const float* __restrict__ post,
                const int* __restrict__ length,
                float* __restrict__ out)
{
    const int bid  = blockIdx.x;
    const int b    = bid / BPR;
    const int c    = bid % BPR;
    const int len  = length[b];       // 1 <= len <= S (int32)
    const int s0   = c * CHUNK;
    const int lane = threadIdx.x & 31;
    const int warp = threadIdx.x >> 5;

    float sum = 0.0f;

    // ---- main body: identical to R11 ----
    const int segbase = s0 + warp * WSEG;

    if (segbase < len) {
        const float2* row  = reinterpret_cast<const float2*>(post)
                             + (size_t)b * S_CONST;
        const float4* rowq = reinterpret_cast<const float4*>(row);
        const int qbase = (segbase >> 1) + lane;   // this lane's first quad

        // Cross-warp-boundary carry: pair at s = segbase-1 (lane 0 only).
        float cr0 = 0.0f, cr1 = 0.0f;
        if (segbase > 0 && lane == 0) {
            float2 pv = row[segbase - 1];
            cr0 = pv.x; cr1 = pv.y;
        }

        if (segbase > 0 && segbase + WSEG <= len) {
            // ---- FAST PATH (warp-uniform): every transition valid. ----
            float4 V[ITERS];
            #pragma unroll
            for (int i = 0; i < ITERS; ++i)
                V[i] = rowq[qbase + i * 32];

            #pragma unroll
            for (int i = 0; i < ITERS; ++i) {
                float c0a = V[i].x, c1a = V[i].y;   // pair at s
                float c0b = V[i].z, c1b = V[i].w;   // pair at s+1

                float pv0 = __shfl_up_sync(FULL, c0b, 1);
                float pv1 = __shfl_up_sync(FULL, c1b, 1);
                if (lane == 0) { pv0 = cr0; pv1 = cr1; }

                float l0a = __logf(c0a), l1a = __logf(c1a);
                float l0b = __logf(c0b), l1b = __logf(c1b);

                sum += div_term_l(pv0, pv1, c0a, c1a, l0a, l1a);
                sum += div_term_l(c0a, c1a, c0b, c1b, l0b, l1b);

                cr0 = __shfl_sync(FULL, c0b, 31);
                cr1 = __shfl_sync(FULL, c1b, 31);
            }
        } else {
            // ---- SLOW PATH: segment contains s==0 or the len cutoff. ----
            float4 V[ITERS];
            #pragma unroll
            for (int i = 0; i < ITERS; ++i)
                if (segbase + i * 64 < len)
                    V[i] = rowq[qbase + i * 32];

            #pragma unroll
            for (int i = 0; i < ITERS; ++i) {
                if (segbase + i * 64 >= len) break;   // warp-uniform

                float c0a = V[i].x, c1a = V[i].y;
                float c0b = V[i].z, c1b = V[i].w;

                float pv0 = __shfl_up_sync(FULL, c0b, 1);
                float pv1 = __shfl_up_sync(FULL, c1b, 1);
                if (lane == 0) { pv0 = cr0; pv1 = cr1; }

                const int sidx = segbase + i * 64 + 2 * lane;

                float l0a = __logf(c0a), l1a = __logf(c1a);
                float l0b = __logf(c0b), l1b = __logf(c1b);

                if (sidx == 0) {
                    // first-term contribution at s = 0 (len >= 1 always)
                    sum += c1a * (l1a - LOG_A) + c0a * (l0a - LOG_1A);
                } else if (sidx < len) {
                    sum += div_term_l(pv0, pv1, c0a, c1a, l0a, l1a);
                }
                if (sidx + 1 < len)
                    sum += div_term_l(c0a, c1a, c0b, c1b, l0b, l1b);

                cr0 = __shfl_sync(FULL, c0b, 31);
                cr1 = __shfl_sync(FULL, c1b, 31);
            }
        }
    }

    // Deterministic block reduction: warp shuffle tree + smem
    #pragma unroll
    for (int off = 16; off > 0; off >>= 1)
        sum += __shfl_down_sync(FULL, sum, off);

    __shared__ float wsum[THREADS / 32];
    if (lane == 0) wsum[warp] = sum;
    __syncthreads();

    if (warp == 0) {
        float v = (lane < THREADS / 32) ? wsum[lane] : 0.0f;
        #pragma unroll
        for (int off = 4; off > 0; off >>= 1)
            v += __shfl_down_sync(FULL, v, off);
        if (lane == 0) {
            // Plain partial store, then NON-RETURNING release increment.
            // Release orders the store before the count becomes visible;
            // no return value -> no serialization wait on our exit path.
            g_partials[bid] = v;
            asm volatile("red.release.gpu.global.add.u32 [%0], %1;"
                         :: "l"(&g_count), "r"(1u) : "memory");
        }
    }

    // ---- spinner: block 0 waits for all partials, reduces, writes out ----
    if (bid == 0) {
        if (threadIdx.x == 0) {
            unsigned int seen;
            do {
                asm volatile("ld.acquire.gpu.global.u32 %0, [%1];"
                             : "=r"(seen) : "l"(&g_count) : "memory");
                if (seen < (unsigned)GRID) __nanosleep(200);
            } while (seen < (unsigned)GRID);
        }
        __syncthreads();   // cta fence: acquire result visible to all threads

        // 4096 partials = 1024 float4; 256 threads x 4 each. Fixed order ->
        // deterministic.
        const float4* p4 = reinterpret_cast<const float4*>(g_partials);
        float s = 0.0f;
        #pragma unroll
        for (int i = 0; i < 4; ++i) {
            float4 a = p4[threadIdx.x + i * THREADS];
            s += (a.x + a.y) + (a.z + a.w);
        }

        #pragma unroll
        for (int off = 16; off > 0; off >>= 1)
            s += __shfl_down_sync(FULL, s, off);

        __shared__ float fsum[THREADS / 32];
        if (lane == 0) fsum[warp] = s;
        __syncthreads();

        if (warp == 0) {
            float v = (lane < THREADS / 32) ? fsum[lane] : 0.0f;
            #pragma unroll
            for (int off = 4; off > 0; off >>= 1)
                v += __shfl_down_sync(FULL, v, off);
            if (lane == 0) {
                out[0]  = v / (float)B_CONST;
                g_count = 0;            // reset for next graph replay
            }
        }
    }
}

extern "C" void kernel_launch(void* const* d_in, const int* in_sizes, int n_in,
                              void* d_out, int out_size)
{
    const float* post = (const float*)d_in[0];   // (B, S, 2) f32 interleaved
    const int*   len  = (const int*)d_in[1];     // (B,) int32 on device
    float*       out  = (float*)d_out;           // scalar f32

    ekl_kernel<<<GRID, THREADS>>>(post, len, out);
}